// round 11
// baseline (speedup 1.0000x reference)
#include <cuda_runtime.h>

// Problem constants (fixed by the dataset: B=8, T=1024, D=8)
#define TT     1024
#define BB     8
#define DD     8
#define DPITCH 2056          // padded so dtw prefetch up to diag 2050 stays in-bounds
#define BIGV   1e30f
#define EPSV   1e-6f
#define NCTA   4             // CTAs per batch in the DTW phase (256 rows each)

// Scratch (allocation-free rule: __device__ globals only).
__device__ float g_diag[(size_t)BB * DPITCH * TT];   // diag-major dist, ~67 MB
__device__ float g_bound[BB][NCTA - 1][2048];        // cross-CTA boundary slots (value-as-flag)
__device__ float g_res[BB];                          // per-batch results (value-as-flag, init -1)

__device__ __forceinline__ float ldg_relaxed(const float* p) {
    float v;
    asm volatile("ld.relaxed.gpu.global.f32 %0, [%1];" : "=f"(v) : "l"(p));
    return v;
}
__device__ __forceinline__ void stg_relaxed(float* p, float v) {
    asm volatile("st.relaxed.gpu.global.f32 [%0], %1;" :: "l"(p), "f"(v));
}

// ---------------------------------------------------------------------------
// Phase 1: pairwise distances, written diagonal-major.
// Block = (batch, k-tile 64, i-tile 64); 256 threads; writes coalesced.
// Block (0,0,b) additionally re-initializes the cross-CTA boundary sentinels
// and g_res[b] for batch b (every launch; stream order puts it before dtw).
// ---------------------------------------------------------------------------
__global__ void __launch_bounds__(256) dist_kernel(const float* __restrict__ obs,
                                                   const float* __restrict__ mod) {
    __shared__ float4 smod[128 * 2];

    const int b  = blockIdx.z;
    const int k0 = blockIdx.y * 64;
    const int i0 = blockIdx.x * 64;
    const int tid = threadIdx.x;

    if (k0 == 0 && i0 == 0) {
        // Sentinel init: slot 0 = BIGV (boundary rows invalid on diag 0), rest -1.
        for (int idx = tid; idx < (NCTA - 1) * 2048; idx += 256) {
            const int c  = idx >> 11;
            const int kk = idx & 2047;
            g_bound[b][c][kk] = (kk == 0) ? BIGV : -1.0f;
        }
        if (tid == 0) g_res[b] = -1.0f;
    }

    const int jlo = k0 - i0 - 63;      // lowest mod row touched by this tile

    {
        const int r = tid >> 1;        // 0..127
        const int h = tid & 1;
        const int j = jlo + r;
        float4 v = make_float4(0.f, 0.f, 0.f, 0.f);
        if (j >= 0 && j < TT)
            v = *reinterpret_cast<const float4*>(mod + ((size_t)b * TT + j) * DD + h * 4);
        smod[r * 2 + h] = v;
    }
    __syncthreads();

    const int il = tid & 63;
    const int kq = tid >> 6;           // 0..3
    const int i  = i0 + il;

    const float4* op = reinterpret_cast<const float4*>(obs + ((size_t)b * TT + i) * DD);
    const float4 o0 = op[0];
    const float4 o1 = op[1];

    float* outbase = g_diag + ((size_t)b * DPITCH) * TT + i;

    #pragma unroll
    for (int kk = 0; kk < 16; kk++) {
        const int kl = kq * 16 + kk;   // 0..63
        const int k  = k0 + kl;
        const int j  = k - i;
        float out = BIGV;
        if (j >= 0 && j < TT) {
            const int jl = 63 + kl - il;          // 0..127
            const float4 m0 = smod[jl * 2];
            const float4 m1 = smod[jl * 2 + 1];
            float d, acc;
            d = o0.x - m0.x + EPSV; acc = d * d;
            d = o0.y - m0.y + EPSV; acc = fmaf(d, d, acc);
            d = o0.z - m0.z + EPSV; acc = fmaf(d, d, acc);
            d = o0.w - m0.w + EPSV; acc = fmaf(d, d, acc);
            d = o1.x - m1.x + EPSV; acc = fmaf(d, d, acc);
            d = o1.y - m1.y + EPSV; acc = fmaf(d, d, acc);
            d = o1.z - m1.z + EPSV; acc = fmaf(d, d, acc);
            d = o1.w - m1.w + EPSV; acc = fmaf(d, d, acc);
            out = sqrtf(acc);
        }
        outbase[(size_t)k * TT] = out;
    }
}

// ---------------------------------------------------------------------------
// Phase 2: DTW wavefront, fully decoupled (no barriers in the main loop).
// Grid (NCTA, BB): CTA c of batch b owns rows 256c..256c+255; 128 threads,
// 2 rows/thread; 4 warps = 1 per SMSP. Registers hold diagonals k-1 (PRV)
// and k-2 (CUR pre-update); descending in-place update (no intra-step chain).
// Intra-CTA warp handoff: smem slot/diag, value-as-flag, warp-uniform spin.
// Inter-CTA handoff: g_bound slots via ld/st.relaxed.gpu (L2-coherent);
// consumer double-buffers 4-step groups so L2 latency is off the chain.
// Flow is one-way (c-1 -> c): acyclic, all 32 CTAs resident -> deadlock-free.
// Final batch-mean is folded in: last CTA per batch publishes g_res[b]
// (value-as-flag); last CTA of batch 0 polls all 8, reduces, writes d_out.
// ---------------------------------------------------------------------------
__global__ void __launch_bounds__(128) dtw_kernel(float* __restrict__ out) {
    __shared__ float bnd[3][2048];     // bnd[w][k]: warp w's top-row value at diag k

    const int c    = blockIdx.x;       // 0..NCTA-1
    const int b    = blockIdx.y;
    const int t    = threadIdx.x;      // 0..127
    const int lane = t & 31;
    const int warp = t >> 5;           // 0..3

    for (int idx = t; idx < 3 * 2048; idx += 128) {
        const int kk = idx & 2047;
        ((float*)bnd)[idx] = (kk == 0) ? BIGV : -1.0f;   // diag-0 boundary rows invalid
    }
    __syncthreads();                   // only barrier in the kernel

    const float* dg = g_diag + (size_t)b * DPITCH * TT + 256 * c + 2 * t;

    // Roles.
    const bool cons_g = (c > 0) && (warp == 0);              // consumes global boundary
    const bool prod_g = (c < NCTA - 1) && (warp == 3) && (lane == 31);
    const bool prod_s = (warp < 3) && (lane == 31);          // produces smem boundary
    float*       gdst = (c < NCTA - 1) ? &g_bound[b][c][0] : 0;
    const float* gsrc = (c > 0)        ? &g_bound[b][c - 1][0] : 0;

    // Diagonal state: B = diag 0, A = diag -1.
    float A[2], B[2];
    A[0] = BIGV; A[1] = BIGV; B[0] = BIGV; B[1] = BIGV;
    if (c == 0 && t == 0) B[0] = dg[0];          // dist(0,0)
    float nb2 = BIGV;                            // neighbor value at diag k-2

    // dist prefetch ring: diagonals 1..4; pref base then points at diag 5.
    float2 pf[4];
    pf[0] = *reinterpret_cast<const float2*>(dg + (size_t)1 * TT);
    pf[1] = *reinterpret_cast<const float2*>(dg + (size_t)2 * TT);
    pf[2] = *reinterpret_cast<const float2*>(dg + (size_t)3 * TT);
    pf[3] = *reinterpret_cast<const float2*>(dg + (size_t)4 * TT);
    const float* pref = dg + (size_t)5 * TT;

    // Boundary double buffers (warp 0 of c>0). For c==0 they stay BIGV so the
    // lane-0 select naturally yields the out-of-range value.
    float gva[4] = {BIGV, BIGV, BIGV, BIGV};
    float gvb[4] = {BIGV, BIGV, BIGV, BIGV};
    if (cons_g) {
        #pragma unroll
        for (int q = 0; q < 4; q++) gva[q] = ldg_relaxed(gsrc + q);  // slots 0..3
    }

#define MIN3(x, y, z) fminf(fminf((x), (y)), (z))

// One diagonal. CBQ = pre-verified boundary value (warp-0 path).
// PFOFF = element offset of diag K+4 from the pref base (compile-time affine
// within the unrolled body -> LDG immediate offsets, no per-step ptr math).
#define DTW_STEP(CUR, PRV, K, Q, CBQ, PFOFF)                                  \
    {                                                                         \
        float sh = __shfl_up_sync(0xffffffffu, PRV[1], 1);                    \
        float bv;                                                             \
        if (warp == 0) {                                                      \
            bv = CBQ;                                                         \
        } else {                                                              \
            volatile float* vp = &bnd[warp - 1][(K) - 1];                     \
            bv = *vp;                                                         \
            while (bv < 0.f) bv = *vp;       /* warp-uniform spin */          \
        }                                                                     \
        float nb1 = (lane == 0) ? bv : sh;                                    \
        float2 d = pf[Q];                                                     \
        pf[Q] = *reinterpret_cast<const float2*>(pref + (PFOFF));             \
        CUR[1] = d.y + MIN3(PRV[1], PRV[0], CUR[0]);                          \
        if (prod_s) *((volatile float*)&bnd[warp][(K)]) = CUR[1];             \
        if (prod_g) stg_relaxed(gdst + (K), CUR[1]);                          \
        CUR[0] = d.x + MIN3(PRV[0], nb1, nb2);                                \
        nb2 = nb1;                                                            \
    }

// 4-step group at odd K using buffer CB (slots K-1..K+2, loaded last group);
// verifies CB, then prefetches NB (slots K+3..K+6) for the group at K+4.
// O = dist prefetch base offset for this group (0 or 4*TT).
#define DTW_GROUP(K, CB, NB, O)                                               \
    {                                                                         \
        if (cons_g) {                                                         \
            _Pragma("unroll")                                                 \
            for (int q = 0; q < 4; q++) {                                     \
                while (CB[q] < 0.f) CB[q] = ldg_relaxed(gsrc + (K) - 1 + q);  \
            }                                                                 \
            _Pragma("unroll")                                                 \
            for (int q = 0; q < 4; q++)                                       \
                NB[q] = ldg_relaxed(gsrc + (K) + 3 + q);                      \
        }                                                                     \
        DTW_STEP(A, B, (K) + 0, 0, CB[0], (O) + 0 * TT)                       \
        DTW_STEP(B, A, (K) + 1, 1, CB[1], (O) + 1 * TT)                       \
        DTW_STEP(A, B, (K) + 2, 2, CB[2], (O) + 2 * TT)                       \
        DTW_STEP(B, A, (K) + 3, 3, CB[3], (O) + 3 * TT)                       \
    }

    // k = 1..2040: 255 iterations of two 4-step groups; pref bumps once per 8.
    int k = 1;
    for (int it = 0; it < 255; it++) {
        DTW_GROUP(k,     gva, gvb, 0)
        DTW_GROUP(k + 4, gvb, gva, 4 * TT)
        pref += (size_t)8 * TT;
        k += 8;
    }
    // k = 2041..2044 (pref at diag 2045): prefetches diags 2045..2048,
    // loads gvb slots 2044..2047.
    DTW_GROUP(2041, gva, gvb, 0)
    // Tail k = 2045, 2046: need slots 2044, 2045 (in gvb); prefetches hit
    // padded diags 2049, 2050 (< DPITCH), never consumed.
    if (cons_g) {
        while (gvb[0] < 0.f) gvb[0] = ldg_relaxed(gsrc + 2044);
        while (gvb[1] < 0.f) gvb[1] = ldg_relaxed(gsrc + 2045);
    }
    DTW_STEP(A, B, 2045, 0, gvb[0], 4 * TT)
    DTW_STEP(B, A, 2046, 1, gvb[1], 5 * TT)
#undef DTW_GROUP
#undef DTW_STEP
#undef MIN3

    // Publish per-batch result; batch 0's last CTA gathers all 8 and writes
    // the mean (fixed-order reduction -> deterministic). All CTAs are
    // co-resident, so polling here cannot deadlock.
    if (c == NCTA - 1) {
        if (t == 127) stg_relaxed(&g_res[b], B[1]);      // row 1023, diag 2046
        if (b == 0 && warp == 3) {
            float v = 0.f;
            if (lane < BB) {
                v = ldg_relaxed(&g_res[lane]);
                while (v < 0.f) v = ldg_relaxed(&g_res[lane]);
            }
            // Fixed-order pairwise sum over lanes 0..7.
            v += __shfl_down_sync(0xffffffffu, v, 4);
            v += __shfl_down_sync(0xffffffffu, v, 2);
            v += __shfl_down_sync(0xffffffffu, v, 1);
            if (lane == 0) out[0] = v * (1.0f / (float)BB);
        }
    }
}

extern "C" void kernel_launch(void* const* d_in, const int* in_sizes, int n_in,
                              void* d_out, int out_size) {
    const float* obs = (const float*)d_in[0];
    const float* mod = (const float*)d_in[1];
    float* out = (float*)d_out;

    dim3 g1(16, 32, BB);               // i-tiles x k-tiles x batch
    dist_kernel<<<g1, 256>>>(obs, mod);
    dtw_kernel<<<dim3(NCTA, BB), 128>>>(out);
}

// round 13
// speedup vs baseline: 1.2128x; 1.2128x over previous
#include <cuda_runtime.h>

// Problem constants (fixed by the dataset: B=8, T=1024, D=8)
#define TT     1024
#define BB     8
#define DD     8
#define DPITCH 2080          // padded: dtw pf prefetch reads up to diag 2062
#define BPITCH 2080          // g_bound slots: boundary prefetch reads up to slot 2063
#define BIGV   1e30f
#define EPSV   1e-6f
#define NCTA   4             // CTAs per batch in the DTW phase (256 rows each)

// Scratch (allocation-free rule: __device__ globals only).
__device__ float g_diag[(size_t)BB * DPITCH * TT];   // diag-major dist, ~68 MB
__device__ float g_bound[BB][NCTA - 1][BPITCH];      // cross-CTA boundary slots (value-as-flag)
__device__ float g_res[BB];                          // per-batch results (value-as-flag, init -1)

__device__ __forceinline__ float ldg_relaxed(const float* p) {
    float v;
    asm volatile("ld.relaxed.gpu.global.f32 %0, [%1];" : "=f"(v) : "l"(p));
    return v;
}
__device__ __forceinline__ void stg_relaxed(float* p, float v) {
    asm volatile("st.relaxed.gpu.global.f32 [%0], %1;" :: "l"(p), "f"(v));
}

// ---------------------------------------------------------------------------
// Phase 1: pairwise distances, written diagonal-major.
// ---------------------------------------------------------------------------
__global__ void __launch_bounds__(256) dist_kernel(const float* __restrict__ obs,
                                                   const float* __restrict__ mod) {
    __shared__ float4 smod[128 * 2];

    const int b  = blockIdx.z;
    const int k0 = blockIdx.y * 64;
    const int i0 = blockIdx.x * 64;
    const int tid = threadIdx.x;

    if (k0 == 0 && i0 == 0) {
        // Sentinel init: slot 0 = BIGV (boundary rows invalid on diag 0), rest -1.
        for (int idx = tid; idx < (NCTA - 1) * BPITCH; idx += 256) {
            const int c  = idx / BPITCH;
            const int kk = idx % BPITCH;
            g_bound[b][c][kk] = (kk == 0) ? BIGV : -1.0f;
        }
        if (tid == 0) g_res[b] = -1.0f;
    }

    const int jlo = k0 - i0 - 63;      // lowest mod row touched by this tile

    {
        const int r = tid >> 1;        // 0..127
        const int h = tid & 1;
        const int j = jlo + r;
        float4 v = make_float4(0.f, 0.f, 0.f, 0.f);
        if (j >= 0 && j < TT)
            v = *reinterpret_cast<const float4*>(mod + ((size_t)b * TT + j) * DD + h * 4);
        smod[r * 2 + h] = v;
    }
    __syncthreads();

    const int il = tid & 63;
    const int kq = tid >> 6;           // 0..3
    const int i  = i0 + il;

    const float4* op = reinterpret_cast<const float4*>(obs + ((size_t)b * TT + i) * DD);
    const float4 o0 = op[0];
    const float4 o1 = op[1];

    float* outbase = g_diag + ((size_t)b * DPITCH) * TT + i;

    #pragma unroll
    for (int kk = 0; kk < 16; kk++) {
        const int kl = kq * 16 + kk;   // 0..63
        const int k  = k0 + kl;
        const int j  = k - i;
        float out = BIGV;
        if (j >= 0 && j < TT) {
            const int jl = 63 + kl - il;          // 0..127
            const float4 m0 = smod[jl * 2];
            const float4 m1 = smod[jl * 2 + 1];
            float d, acc;
            d = o0.x - m0.x + EPSV; acc = d * d;
            d = o0.y - m0.y + EPSV; acc = fmaf(d, d, acc);
            d = o0.z - m0.z + EPSV; acc = fmaf(d, d, acc);
            d = o0.w - m0.w + EPSV; acc = fmaf(d, d, acc);
            d = o1.x - m1.x + EPSV; acc = fmaf(d, d, acc);
            d = o1.y - m1.y + EPSV; acc = fmaf(d, d, acc);
            d = o1.z - m1.z + EPSV; acc = fmaf(d, d, acc);
            d = o1.w - m1.w + EPSV; acc = fmaf(d, d, acc);
            out = sqrtf(acc);
        }
        outbase[(size_t)k * TT] = out;
    }
}

// ---------------------------------------------------------------------------
// Phase 2: DTW wavefront, decoupled, DEEP-PREFETCHED (R11 profile showed
// 360 cyc/step = DRAM-latency-bound with only 4-deep prefetch).
// - dist pf ring: 16 diagonals deep (step floor ~ lat/16).
// - inter-CTA boundary: supersteps of 16 slots, double-buffered -> 16-32
//   steps of lookahead (covers L2 store-to-load RT).
// ---------------------------------------------------------------------------
__global__ void __launch_bounds__(128) dtw_kernel(float* __restrict__ out) {
    __shared__ float bnd[3][2048];     // bnd[w][k]: warp w's top-row value at diag k

    const int c    = blockIdx.x;       // 0..NCTA-1
    const int b    = blockIdx.y;
    const int t    = threadIdx.x;      // 0..127
    const int lane = t & 31;
    const int warp = t >> 5;           // 0..3

    for (int idx = t; idx < 3 * 2048; idx += 128) {
        const int kk = idx & 2047;
        ((float*)bnd)[idx] = (kk == 0) ? BIGV : -1.0f;   // diag-0 boundary rows invalid
    }
    __syncthreads();                   // only barrier in the kernel

    const float* dg = g_diag + (size_t)b * DPITCH * TT + 256 * c + 2 * t;

    // Roles.
    const bool cons_g = (c > 0) && (warp == 0);              // consumes global boundary
    const bool prod_g = (c < NCTA - 1) && (warp == 3) && (lane == 31);
    const bool prod_s = (warp < 3) && (lane == 31);          // produces smem boundary
    float*       gdst = (c < NCTA - 1) ? &g_bound[b][c][0] : 0;
    const float* gsrc = (c > 0)        ? &g_bound[b][c - 1][0] : 0;

    // Diagonal state: B = diag 0, A = diag -1.
    float A[2], B[2];
    A[0] = BIGV; A[1] = BIGV; B[0] = BIGV; B[1] = BIGV;
    if (c == 0 && t == 0) B[0] = dg[0];          // dist(0,0)
    float nb2 = BIGV;                            // neighbor value at diag k-2

    // dist prefetch ring: 16 deep (diagonals 1..16); pref then points at 17.
    float2 pf[16];
    #pragma unroll
    for (int q = 0; q < 16; q++)
        pf[q] = *reinterpret_cast<const float2*>(dg + (size_t)(1 + q) * TT);
    const float* pref = dg + (size_t)17 * TT;

    // Boundary double buffers, 16 slots each (warp 0 of c>0). For c==0 they
    // stay BIGV so the lane-0 select naturally yields the out-of-range value.
    float ba[16], bb[16];
    #pragma unroll
    for (int q = 0; q < 16; q++) { ba[q] = BIGV; bb[q] = BIGV; }
    if (cons_g) {
        #pragma unroll
        for (int q = 0; q < 16; q++) ba[q] = ldg_relaxed(gsrc + q);       // slots 0..15
        #pragma unroll
        for (int q = 0; q < 16; q++) bb[q] = ldg_relaxed(gsrc + 16 + q);  // slots 16..31
    }

#define MIN3(x, y, z) fminf(fminf((x), (y)), (z))

// One diagonal. CBQ = pre-verified boundary value (warp-0 path).
// PFOFF = element offset of the reloaded diagonal from the pref base.
#define DTW_STEP(CUR, PRV, K, Q, CBQ, PFOFF)                                  \
    {                                                                         \
        float sh = __shfl_up_sync(0xffffffffu, PRV[1], 1);                    \
        float bv;                                                             \
        if (warp == 0) {                                                      \
            bv = CBQ;                                                         \
        } else {                                                              \
            volatile float* vp = &bnd[warp - 1][(K) - 1];                     \
            bv = *vp;                                                         \
            while (bv < 0.f) bv = *vp;       /* warp-uniform spin */          \
        }                                                                     \
        float nb1 = (lane == 0) ? bv : sh;                                    \
        float2 d = pf[Q];                                                     \
        pf[Q] = *reinterpret_cast<const float2*>(pref + (PFOFF));             \
        CUR[1] = d.y + MIN3(PRV[1], PRV[0], CUR[0]);                          \
        if (prod_s) *((volatile float*)&bnd[warp][(K)]) = CUR[1];             \
        if (prod_g) stg_relaxed(gdst + (K), CUR[1]);                          \
        CUR[0] = d.x + MIN3(PRV[0], nb1, nb2);                                \
        nb2 = nb1;                                                            \
    }

// 16-step superstep at odd K (K ≡ 1 mod 16). CB holds slots K-1..K+14
// (verified here); after consumption, CB is refilled with slots K+31..K+46
// for the superstep at K+32 -> 16..32 steps of boundary lookahead.
// O = pf reload base offset for this superstep (0 or 16*TT).
#define SUPERSTEP(K, CB, O)                                                   \
    {                                                                         \
        if (cons_g) {                                                         \
            _Pragma("unroll")                                                 \
            for (int q = 0; q < 16; q++) {                                    \
                while (CB[q] < 0.f) CB[q] = ldg_relaxed(gsrc + (K) - 1 + q);  \
            }                                                                 \
        }                                                                     \
        DTW_STEP(A, B, (K) +  0,  0, CB[ 0], (O) +  0 * TT)                   \
        DTW_STEP(B, A, (K) +  1,  1, CB[ 1], (O) +  1 * TT)                   \
        DTW_STEP(A, B, (K) +  2,  2, CB[ 2], (O) +  2 * TT)                   \
        DTW_STEP(B, A, (K) +  3,  3, CB[ 3], (O) +  3 * TT)                   \
        DTW_STEP(A, B, (K) +  4,  4, CB[ 4], (O) +  4 * TT)                   \
        DTW_STEP(B, A, (K) +  5,  5, CB[ 5], (O) +  5 * TT)                   \
        DTW_STEP(A, B, (K) +  6,  6, CB[ 6], (O) +  6 * TT)                   \
        DTW_STEP(B, A, (K) +  7,  7, CB[ 7], (O) +  7 * TT)                   \
        DTW_STEP(A, B, (K) +  8,  8, CB[ 8], (O) +  8 * TT)                   \
        DTW_STEP(B, A, (K) +  9,  9, CB[ 9], (O) +  9 * TT)                   \
        DTW_STEP(A, B, (K) + 10, 10, CB[10], (O) + 10 * TT)                   \
        DTW_STEP(B, A, (K) + 11, 11, CB[11], (O) + 11 * TT)                   \
        DTW_STEP(A, B, (K) + 12, 12, CB[12], (O) + 12 * TT)                   \
        DTW_STEP(B, A, (K) + 13, 13, CB[13], (O) + 13 * TT)                   \
        DTW_STEP(A, B, (K) + 14, 14, CB[14], (O) + 14 * TT)                   \
        DTW_STEP(B, A, (K) + 15, 15, CB[15], (O) + 15 * TT)                   \
        if (cons_g) {                                                         \
            _Pragma("unroll")                                                 \
            for (int q = 0; q < 16; q++)                                      \
                CB[q] = ldg_relaxed(gsrc + (K) + 31 + q);                     \
        }                                                                     \
    }

    // k = 1..2016: 63 iterations of two 16-step supersteps.
    int k = 1;
    for (int it = 0; it < 63; it++) {
        SUPERSTEP(k,      ba, 0)
        SUPERSTEP(k + 16, bb, 16 * TT)
        pref += (size_t)32 * TT;
        k += 32;
    }
    // k = 2017..2032: superstep using ba (slots 2016..2031, prefetched at
    // K=1985). Its refill reads slots 2048..2063 (< BPITCH, never consumed).
    // pf reloads fetch diags 2033..2048 for the tail.
    SUPERSTEP(k, ba, 0)
    k += 16;   // k = 2033
    // Tail k = 2033..2046 (14 steps) using bb slots 2032..2045 (prefetched at
    // K=2001). pf reloads read diags 2049..2062 (< DPITCH, never consumed).
    if (cons_g) {
        #pragma unroll
        for (int q = 0; q < 14; q++) {
            while (bb[q] < 0.f) bb[q] = ldg_relaxed(gsrc + 2032 + q);
        }
    }
    DTW_STEP(A, B, k +  0,  0, bb[ 0], (16 +  0) * TT)
    DTW_STEP(B, A, k +  1,  1, bb[ 1], (16 +  1) * TT)
    DTW_STEP(A, B, k +  2,  2, bb[ 2], (16 +  2) * TT)
    DTW_STEP(B, A, k +  3,  3, bb[ 3], (16 +  3) * TT)
    DTW_STEP(A, B, k +  4,  4, bb[ 4], (16 +  4) * TT)
    DTW_STEP(B, A, k +  5,  5, bb[ 5], (16 +  5) * TT)
    DTW_STEP(A, B, k +  6,  6, bb[ 6], (16 +  6) * TT)
    DTW_STEP(B, A, k +  7,  7, bb[ 7], (16 +  7) * TT)
    DTW_STEP(A, B, k +  8,  8, bb[ 8], (16 +  8) * TT)
    DTW_STEP(B, A, k +  9,  9, bb[ 9], (16 +  9) * TT)
    DTW_STEP(A, B, k + 10, 10, bb[10], (16 + 10) * TT)
    DTW_STEP(B, A, k + 11, 11, bb[11], (16 + 11) * TT)
    DTW_STEP(A, B, k + 12, 12, bb[12], (16 + 12) * TT)
    DTW_STEP(B, A, k + 13, 13, bb[13], (16 + 13) * TT)   // k+13 = 2046, writes B
#undef SUPERSTEP
#undef DTW_STEP
#undef MIN3

    // Publish per-batch result; batch 0's last CTA gathers all 8 and writes
    // the mean (fixed-order reduction -> deterministic). All CTAs are
    // co-resident, so polling here cannot deadlock.
    if (c == NCTA - 1) {
        if (t == 127) stg_relaxed(&g_res[b], B[1]);      // row 1023, diag 2046
        if (b == 0 && warp == 3) {
            float v = 0.f;
            if (lane < BB) {
                v = ldg_relaxed(&g_res[lane]);
                while (v < 0.f) v = ldg_relaxed(&g_res[lane]);
            }
            // Fixed-order pairwise sum over lanes 0..7.
            v += __shfl_down_sync(0xffffffffu, v, 4);
            v += __shfl_down_sync(0xffffffffu, v, 2);
            v += __shfl_down_sync(0xffffffffu, v, 1);
            if (lane == 0) out[0] = v * (1.0f / (float)BB);
        }
    }
}

extern "C" void kernel_launch(void* const* d_in, const int* in_sizes, int n_in,
                              void* d_out, int out_size) {
    const float* obs = (const float*)d_in[0];
    const float* mod = (const float*)d_in[1];
    float* out = (float*)d_out;

    dim3 g1(16, 32, BB);               // i-tiles x k-tiles x batch
    dist_kernel<<<g1, 256>>>(obs, mod);
    dtw_kernel<<<dim3(NCTA, BB), 128>>>(out);
}

// round 14
// speedup vs baseline: 1.9939x; 1.6441x over previous
#include <cuda_runtime.h>

// Problem constants (fixed by the dataset: B=8, T=1024, D=8)
#define TT     1024
#define BB     8
#define DD     8
#define DPITCH 2080          // pf refill reads up to diag 2064
#define BPITCH 2080          // boundary refill reads up to slot 2063
#define BIGV   1e30f
#define EPSV   1e-6f
#define NCTA   4             // CTAs per batch in the DTW phase (256 rows each)

// Scratch (allocation-free rule: __device__ globals only).
__device__ float g_diag[(size_t)BB * DPITCH * TT];   // diag-major dist, ~68 MB
__device__ float g_bound[BB][NCTA - 1][BPITCH];      // cross-CTA boundary slots (value-as-flag)
__device__ float g_res[BB];                          // per-batch results (value-as-flag, init -1)

__device__ __forceinline__ float ldg_relaxed(const float* p) {
    float v;
    asm volatile("ld.relaxed.gpu.global.f32 %0, [%1];" : "=f"(v) : "l"(p));
    return v;
}
__device__ __forceinline__ void stg_relaxed(float* p, float v) {
    asm volatile("st.relaxed.gpu.global.f32 [%0], %1;" :: "l"(p), "f"(v));
}

// ---------------------------------------------------------------------------
// Phase 1: pairwise distances, written diagonal-major. (unchanged)
// ---------------------------------------------------------------------------
__global__ void __launch_bounds__(256) dist_kernel(const float* __restrict__ obs,
                                                   const float* __restrict__ mod) {
    __shared__ float4 smod[128 * 2];

    const int b  = blockIdx.z;
    const int k0 = blockIdx.y * 64;
    const int i0 = blockIdx.x * 64;
    const int tid = threadIdx.x;

    if (k0 == 0 && i0 == 0) {
        for (int idx = tid; idx < (NCTA - 1) * BPITCH; idx += 256) {
            const int c  = idx / BPITCH;
            const int kk = idx % BPITCH;
            g_bound[b][c][kk] = (kk == 0) ? BIGV : -1.0f;
        }
        if (tid == 0) g_res[b] = -1.0f;
    }

    const int jlo = k0 - i0 - 63;

    {
        const int r = tid >> 1;
        const int h = tid & 1;
        const int j = jlo + r;
        float4 v = make_float4(0.f, 0.f, 0.f, 0.f);
        if (j >= 0 && j < TT)
            v = *reinterpret_cast<const float4*>(mod + ((size_t)b * TT + j) * DD + h * 4);
        smod[r * 2 + h] = v;
    }
    __syncthreads();

    const int il = tid & 63;
    const int kq = tid >> 6;
    const int i  = i0 + il;

    const float4* op = reinterpret_cast<const float4*>(obs + ((size_t)b * TT + i) * DD);
    const float4 o0 = op[0];
    const float4 o1 = op[1];

    float* outbase = g_diag + ((size_t)b * DPITCH) * TT + i;

    #pragma unroll
    for (int kk = 0; kk < 16; kk++) {
        const int kl = kq * 16 + kk;
        const int k  = k0 + kl;
        const int j  = k - i;
        float out = BIGV;
        if (j >= 0 && j < TT) {
            const int jl = 63 + kl - il;
            const float4 m0 = smod[jl * 2];
            const float4 m1 = smod[jl * 2 + 1];
            float d, acc;
            d = o0.x - m0.x + EPSV; acc = d * d;
            d = o0.y - m0.y + EPSV; acc = fmaf(d, d, acc);
            d = o0.z - m0.z + EPSV; acc = fmaf(d, d, acc);
            d = o0.w - m0.w + EPSV; acc = fmaf(d, d, acc);
            d = o1.x - m1.x + EPSV; acc = fmaf(d, d, acc);
            d = o1.y - m1.y + EPSV; acc = fmaf(d, d, acc);
            d = o1.z - m1.z + EPSV; acc = fmaf(d, d, acc);
            d = o1.w - m1.w + EPSV; acc = fmaf(d, d, acc);
            out = sqrtf(acc);
        }
        outbase[(size_t)k * TT] = out;
    }
}

// ---------------------------------------------------------------------------
// Phase 2: DTW wavefront, decoupled, SUPERSTEP-BATCHED.
// R13 post-mortem: per-step rolling LDG prefetch was SB-slot-serialized
// (effective lookahead ~6 steps) and the per-step smem poll put a full
// LDS latency on every step. Fix: batch at 16-step superstep granularity:
//  - dist pf: two 16-diag register banks, burst refill once per superstep,
//    consumed 16-31 steps later (one batched wait per superstep).
//  - smem boundary (warps 1-3): 16 pipelined LDS up front, verify after,
//    re-poll only stragglers.
//  - global boundary (warp 0, c>0): existing double-buffered 16-slot scheme.
// ---------------------------------------------------------------------------
__global__ void __launch_bounds__(128) dtw_kernel(float* __restrict__ out) {
    __shared__ float bnd[3][2048];     // bnd[w][k]: warp w's top-row value at diag k

    const int c    = blockIdx.x;       // 0..NCTA-1
    const int b    = blockIdx.y;
    const int t    = threadIdx.x;      // 0..127
    const int lane = t & 31;
    const int warp = t >> 5;           // 0..3

    for (int idx = t; idx < 3 * 2048; idx += 128) {
        const int kk = idx & 2047;
        ((float*)bnd)[idx] = (kk == 0) ? BIGV : -1.0f;   // diag-0 boundary rows invalid
    }
    __syncthreads();                   // only barrier in the kernel

    const float* dg = g_diag + (size_t)b * DPITCH * TT + 256 * c + 2 * t;

    // Roles.
    const bool cons_g = (c > 0) && (warp == 0);
    const bool prod_g = (c < NCTA - 1) && (warp == 3) && (lane == 31);
    const bool prod_s = (warp < 3) && (lane == 31);
    float*       gdst = (c < NCTA - 1) ? &g_bound[b][c][0] : 0;
    const float* gsrc = (c > 0)        ? &g_bound[b][c - 1][0] : 0;

    // Diagonal state: B = diag 0, A = diag -1.
    float A[2], B[2];
    A[0] = BIGV; A[1] = BIGV; B[0] = BIGV; B[1] = BIGV;
    if (c == 0 && t == 0) B[0] = dg[0];          // dist(0,0)
    float nb2 = BIGV;

    // dist prefetch banks: pa = diags 1..16 (superstep 1), pb = 17..32.
    float2 pa[16], pb[16];
    #pragma unroll
    for (int q = 0; q < 16; q++)
        pa[q] = *reinterpret_cast<const float2*>(dg + (size_t)(1 + q) * TT);
    #pragma unroll
    for (int q = 0; q < 16; q++)
        pb[q] = *reinterpret_cast<const float2*>(dg + (size_t)(17 + q) * TT);
    const float* pref = dg + (size_t)33 * TT;    // next refill target: diag 33

    // Global-boundary double buffers (warp 0 of c>0).
    float ba[16], bb[16];
    #pragma unroll
    for (int q = 0; q < 16; q++) { ba[q] = BIGV; bb[q] = BIGV; }
    if (cons_g) {
        #pragma unroll
        for (int q = 0; q < 16; q++) ba[q] = ldg_relaxed(gsrc + q);       // slots 0..15
        #pragma unroll
        for (int q = 0; q < 16; q++) bb[q] = ldg_relaxed(gsrc + 16 + q);  // slots 16..31
    }

#define MIN3(x, y, z) fminf(fminf((x), (y)), (z))

// One diagonal KK, consuming bank entry PF[M] and boundary value nbv[M].
#define DTW_STEP(CUR, PRV, KK, PF, M)                                        \
    {                                                                        \
        float sh  = __shfl_up_sync(0xffffffffu, PRV[1], 1);                  \
        float nb1 = (lane == 0) ? nbv[M] : sh;                               \
        float2 d  = PF[M];                                                   \
        CUR[1] = d.y + MIN3(PRV[1], PRV[0], CUR[0]);                         \
        if (prod_s) *((volatile float*)&bnd[warp][(KK)]) = CUR[1];           \
        if (prod_g) stg_relaxed(gdst + (KK), CUR[1]);                        \
        CUR[0] = d.x + MIN3(PRV[0], nb1, nb2);                               \
        nb2 = nb1;                                                           \
    }

// 16-step superstep at K (odd). CB = warp-0 boundary bank (slots K-1..K+14,
// prefetched 2 supersteps ago, verified here; refilled after with K+31..K+46).
// PF = dist bank (diags K..K+15, loaded 2 supersteps ago; refilled after with
// diags K+32..K+47 via pref). Warps 1-3 batch-read bnd[warp-1][K-1..K+14].
#define SUPERSTEP(K, CB, PF)                                                 \
    {                                                                        \
        float nbv[16];                                                       \
        if (warp == 0) {                                                     \
            if (cons_g) {                                                    \
                _Pragma("unroll")                                            \
                for (int q = 0; q < 16; q++) {                               \
                    while (CB[q] < 0.f)                                      \
                        CB[q] = ldg_relaxed(gsrc + (K) - 1 + q);             \
                }                                                            \
            }                                                                \
            _Pragma("unroll")                                                \
            for (int q = 0; q < 16; q++) nbv[q] = CB[q];                     \
        } else {                                                             \
            volatile float* vsrc = &bnd[warp - 1][(K) - 1];                  \
            _Pragma("unroll")                                                \
            for (int q = 0; q < 16; q++) nbv[q] = vsrc[q];                   \
            _Pragma("unroll")                                                \
            for (int q = 0; q < 16; q++) {                                   \
                while (nbv[q] < 0.f) nbv[q] = vsrc[q];                       \
            }                                                                \
        }                                                                    \
        DTW_STEP(A, B, (K) +  0, PF,  0)                                     \
        DTW_STEP(B, A, (K) +  1, PF,  1)                                     \
        DTW_STEP(A, B, (K) +  2, PF,  2)                                     \
        DTW_STEP(B, A, (K) +  3, PF,  3)                                     \
        DTW_STEP(A, B, (K) +  4, PF,  4)                                     \
        DTW_STEP(B, A, (K) +  5, PF,  5)                                     \
        DTW_STEP(A, B, (K) +  6, PF,  6)                                     \
        DTW_STEP(B, A, (K) +  7, PF,  7)                                     \
        DTW_STEP(A, B, (K) +  8, PF,  8)                                     \
        DTW_STEP(B, A, (K) +  9, PF,  9)                                     \
        DTW_STEP(A, B, (K) + 10, PF, 10)                                     \
        DTW_STEP(B, A, (K) + 11, PF, 11)                                     \
        DTW_STEP(A, B, (K) + 12, PF, 12)                                     \
        DTW_STEP(B, A, (K) + 13, PF, 13)                                     \
        DTW_STEP(A, B, (K) + 14, PF, 14)                                     \
        DTW_STEP(B, A, (K) + 15, PF, 15)                                     \
        if (cons_g) {                                                        \
            _Pragma("unroll")                                                \
            for (int q = 0; q < 16; q++)                                     \
                CB[q] = ldg_relaxed(gsrc + (K) + 31 + q);                    \
        }                                                                    \
        _Pragma("unroll")                                                    \
        for (int q = 0; q < 16; q++)                                         \
            PF[q] = *reinterpret_cast<const float2*>(pref + (size_t)q * TT); \
        pref += (size_t)16 * TT;                                             \
    }

    // k = 1..2016: 63 iterations of two supersteps (banks alternate).
    int k = 1;
    for (int it = 0; it < 63; it++) {
        SUPERSTEP(k,      ba, pa)
        SUPERSTEP(k + 16, bb, pb)
        k += 32;
    }
    // k = 2017..2032: superstep on (ba, pa); ba holds slots 2016..2031
    // (refilled at K=1985), pa holds diags 2017..2032 (refilled at K=1985).
    // Its refills read slot 2063 / diag 2064 max (< pitches, never consumed).
    SUPERSTEP(k, ba, pa)
    k += 16;   // 2033

    // Tail: 14 steps k = 2033..2046. pb holds diags 2033..2048 (refilled at
    // K=2001); bb holds slots 2032..2047 (refilled at K=2001).
    {
        float nbv[16];
        if (warp == 0) {
            if (cons_g) {
                #pragma unroll
                for (int q = 0; q < 14; q++) {
                    while (bb[q] < 0.f) bb[q] = ldg_relaxed(gsrc + 2032 + q);
                }
            }
            #pragma unroll
            for (int q = 0; q < 14; q++) nbv[q] = bb[q];
        } else {
            volatile float* vsrc = &bnd[warp - 1][2032];
            #pragma unroll
            for (int q = 0; q < 14; q++) nbv[q] = vsrc[q];
            #pragma unroll
            for (int q = 0; q < 14; q++) {
                while (nbv[q] < 0.f) nbv[q] = vsrc[q];
            }
        }
        DTW_STEP(A, B, 2033, pb,  0)
        DTW_STEP(B, A, 2034, pb,  1)
        DTW_STEP(A, B, 2035, pb,  2)
        DTW_STEP(B, A, 2036, pb,  3)
        DTW_STEP(A, B, 2037, pb,  4)
        DTW_STEP(B, A, 2038, pb,  5)
        DTW_STEP(A, B, 2039, pb,  6)
        DTW_STEP(B, A, 2040, pb,  7)
        DTW_STEP(A, B, 2041, pb,  8)
        DTW_STEP(B, A, 2042, pb,  9)
        DTW_STEP(A, B, 2043, pb, 10)
        DTW_STEP(B, A, 2044, pb, 11)
        DTW_STEP(A, B, 2045, pb, 12)
        DTW_STEP(B, A, 2046, pb, 13)   // final diagonal, writes B
    }
#undef SUPERSTEP
#undef DTW_STEP
#undef MIN3

    // Publish per-batch result; batch 0's last CTA gathers all 8 and writes
    // the mean (fixed-order reduction -> deterministic).
    if (c == NCTA - 1) {
        if (t == 127) stg_relaxed(&g_res[b], B[1]);      // row 1023, diag 2046
        if (b == 0 && warp == 3) {
            float v = 0.f;
            if (lane < BB) {
                v = ldg_relaxed(&g_res[lane]);
                while (v < 0.f) v = ldg_relaxed(&g_res[lane]);
            }
            v += __shfl_down_sync(0xffffffffu, v, 4);
            v += __shfl_down_sync(0xffffffffu, v, 2);
            v += __shfl_down_sync(0xffffffffu, v, 1);
            if (lane == 0) out[0] = v * (1.0f / (float)BB);
        }
    }
}

extern "C" void kernel_launch(void* const* d_in, const int* in_sizes, int n_in,
                              void* d_out, int out_size) {
    const float* obs = (const float*)d_in[0];
    const float* mod = (const float*)d_in[1];
    float* out = (float*)d_out;

    dim3 g1(16, 32, BB);               // i-tiles x k-tiles x batch
    dist_kernel<<<g1, 256>>>(obs, mod);
    dtw_kernel<<<dim3(NCTA, BB), 128>>>(out);
}